// round 4
// baseline (speedup 1.0000x reference)
#include <cuda_runtime.h>
#include <cuda_bf16.h>
#include <math.h>

// ---------------------------------------------------------------------------
// Problem constants (MultiScaleDeformableAttention)
// ---------------------------------------------------------------------------
#define BS      2
#define EMBED   256
#define HEADS   8
#define LEVELS  4
#define POINTS  4
#define NEMBED  32          // EMBED / HEADS
#define LEN_V   18360       // sum of h*w over SHAPES
#define LEN_Q   18360
#define MROWS   (BS * LEN_Q)        // 36720
#define KDIM    256

// level shapes (h, w): (96,144) (48,72) (24,36) (12,18)
__device__ __constant__ int c_lw[4]     = {144, 72, 36, 18};
__device__ __constant__ int c_lh[4]     = { 96, 48, 24, 12};
__device__ __constant__ int c_lstart[4] = {0, 13824, 17280, 18144};

// ---------------------------------------------------------------------------
// Device scratch (allocation-free)
// ---------------------------------------------------------------------------
__device__ float g_vproj[BS * HEADS * LEN_V * NEMBED];     // [(b*8+h)][lv][32]
__device__ float g_off  [MROWS * 256];                     // raw offset gemm out
__device__ float g_aw   [MROWS * 128];                     // logits -> softmaxed in place
__device__ float g_loc  [MROWS * HEADS * LEVELS * POINTS * 2]; // [(r*8+h)][32]
__device__ float g_x    [MROWS * 256];                     // sampled features [b,q,h*32+d]

// ---------------------------------------------------------------------------
// Generic fp32 tiled GEMM: C = A[M,256] * B[256,N]  (+ epilogue variants)
// BM=128 BN=128 BK=8, 256 threads, 8x8 per-thread microtile
// MODE 0: C[row*N+col] = acc                      (raw store)
// MODE 1: vproj scatter: + bias, mask, layout [(b*8+h)][lv][d]
// MODE 2: C[row*N+col] = acc + bias[col]          (out projection)
// ---------------------------------------------------------------------------
template <int MODE>
__global__ __launch_bounds__(256)
void sgemm_kernel(const float* __restrict__ A,
                  const float* __restrict__ Bm,
                  float* __restrict__ C,
                  int M, int N,
                  const float* __restrict__ bias,
                  const int* __restrict__ mask)
{
    constexpr int BM = 128, BN = 128, BK = 8;
    __shared__ float As[BK][BM + 4];   // stride 132 floats (16B aligned, bank-safe)
    __shared__ float Bs[BK][BN];

    const int tid  = threadIdx.x;
    const int row0 = blockIdx.y * BM;
    const int col0 = blockIdx.x * BN;

    const int arow = tid >> 1;          // 0..127
    const int acol = (tid & 1) * 4;     // 0 or 4
    const int brow = tid >> 5;          // 0..7
    const int bcol = (tid & 31) * 4;    // 0..124

    const int tx = tid & 15;            // 0..15 -> 8 cols each
    const int ty = tid >> 4;            // 0..15 -> 8 rows each

    float acc[8][8];
#pragma unroll
    for (int i = 0; i < 8; i++)
#pragma unroll
        for (int j = 0; j < 8; j++) acc[i][j] = 0.f;

    for (int k0 = 0; k0 < KDIM; k0 += BK) {
        // load A tile (128 x 8), transposed into As
        float4 a4 = make_float4(0.f, 0.f, 0.f, 0.f);
        if (row0 + arow < M)
            a4 = *reinterpret_cast<const float4*>(A + (size_t)(row0 + arow) * KDIM + k0 + acol);
        As[acol + 0][arow] = a4.x;
        As[acol + 1][arow] = a4.y;
        As[acol + 2][arow] = a4.z;
        As[acol + 3][arow] = a4.w;
        // load B tile (8 x 128)
        float4 b4 = *reinterpret_cast<const float4*>(Bm + (size_t)(k0 + brow) * N + col0 + bcol);
        *reinterpret_cast<float4*>(&Bs[brow][bcol]) = b4;
        __syncthreads();

#pragma unroll
        for (int k = 0; k < BK; k++) {
            float a[8], b[8];
            *reinterpret_cast<float4*>(&a[0]) = *reinterpret_cast<const float4*>(&As[k][ty * 8 + 0]);
            *reinterpret_cast<float4*>(&a[4]) = *reinterpret_cast<const float4*>(&As[k][ty * 8 + 4]);
            *reinterpret_cast<float4*>(&b[0]) = *reinterpret_cast<const float4*>(&Bs[k][tx * 8 + 0]);
            *reinterpret_cast<float4*>(&b[4]) = *reinterpret_cast<const float4*>(&Bs[k][tx * 8 + 4]);
#pragma unroll
            for (int i = 0; i < 8; i++)
#pragma unroll
                for (int j = 0; j < 8; j++)
                    acc[i][j] = fmaf(a[i], b[j], acc[i][j]);
        }
        __syncthreads();
    }

    // epilogue
#pragma unroll
    for (int i = 0; i < 8; i++) {
        int row = row0 + ty * 8 + i;
        if (row >= M) continue;
#pragma unroll
        for (int j = 0; j < 8; j++) {
            int col = col0 + tx * 8 + j;
            float v = acc[i][j];
            if (MODE == 0) {
                C[(size_t)row * N + col] = v;
            } else if (MODE == 1) {
                // v-projection scatter: row=(b,lv), col=(h,d)
                v += bias[col];
                if (mask[row] == 0) v = 0.f;   // pad_mask is int32 (bool -> int32)
                int b  = row / LEN_V;
                int lv = row - b * LEN_V;
                int h  = col >> 5;
                int d  = col & 31;
                g_vproj[(((size_t)(b * HEADS + h)) * LEN_V + lv) * NEMBED + d] = v;
            } else { // MODE == 2
                C[(size_t)row * N + col] = v + bias[col];
            }
        }
    }
}

// ---------------------------------------------------------------------------
// Softmax over 16 points per (b,q,h) + sampling-location computation.
// One warp per task; tasks = MROWS * HEADS.
// ---------------------------------------------------------------------------
__global__ __launch_bounds__(256)
void softmax_loc_kernel(const float* __restrict__ ab,     // (8,16)
                        const float* __restrict__ sob,    // (8,4,4,2) = 256
                        const float* __restrict__ refp)   // (B,Q,4,2)
{
    int task = blockIdx.x * (blockDim.x >> 5) + (threadIdx.x >> 5);
    if (task >= MROWS * HEADS) return;
    const int lane = threadIdx.x & 31;
    const int h = task & 7;
    const int r = task >> 3;     // b*Q + q

    // --- softmax over 16 logits ---
    float logit = -1e30f;
    if (lane < 16) logit = g_aw[(size_t)r * 128 + h * 16 + lane] + ab[h * 16 + lane];
    float m = logit;
#pragma unroll
    for (int o = 8; o > 0; o >>= 1) m = fmaxf(m, __shfl_xor_sync(0xffffffffu, m, o));
    float e = (lane < 16) ? expf(logit - m) : 0.f;
    float s = e;
#pragma unroll
    for (int o = 8; o > 0; o >>= 1) s += __shfl_xor_sync(0xffffffffu, s, o);
    if (lane < 16) g_aw[(size_t)r * 128 + h * 16 + lane] = e / s;

    // --- sampling locations: lane indexes (l,p,c), 32 entries ---
    const int c  = lane & 1;
    const int lp = lane >> 1;
    const int l  = lp >> 2;
    float off = g_off[(size_t)r * 256 + h * 32 + lane] + sob[h * 32 + lane];
    float norm = (c == 0) ? (float)c_lw[l] : (float)c_lh[l];
    float rp = refp[((size_t)r * 4 + l) * 2 + c];
    g_loc[(size_t)task * 32 + lane] = rp + off / norm;
}

// ---------------------------------------------------------------------------
// Bilinear sampling + attention weighting.
// One warp per (b,q,h); lane = channel d (32 channels -> 128B coalesced lines).
// ---------------------------------------------------------------------------
__global__ __launch_bounds__(256)
void sampling_kernel()
{
    int task = blockIdx.x * (blockDim.x >> 5) + (threadIdx.x >> 5);
    if (task >= MROWS * HEADS) return;
    const int lane = threadIdx.x & 31;
    const int h = task & 7;
    const int r = task >> 3;
    const int b = (r >= LEN_Q) ? 1 : 0;

    const float locv = g_loc[(size_t)task * 32 + lane];
    const float awv  = (lane < 16) ? g_aw[(size_t)r * 128 + h * 16 + lane] : 0.f;
    const float* __restrict__ vb = g_vproj + ((size_t)(b * HEADS + h)) * LEN_V * NEMBED;

    float acc = 0.f;
#pragma unroll
    for (int sIdx = 0; sIdx < LEVELS * POINTS; sIdx++) {
        const int l = sIdx >> 2;
        const int w = c_lw[l], hh = c_lh[l], st = c_lstart[l];
        const float gx = __shfl_sync(0xffffffffu, locv, 2 * sIdx);
        const float gy = __shfl_sync(0xffffffffu, locv, 2 * sIdx + 1);
        const float a  = __shfl_sync(0xffffffffu, awv, sIdx);

        const float x = gx * (float)w - 0.5f;
        const float y = gy * (float)hh - 0.5f;
        const float xf = floorf(x), yf = floorf(y);
        const int x0 = (int)xf, y0 = (int)yf;
        const float dx = x - xf, dy = y - yf;

        const bool bx0 = (x0 >= 0) && (x0 <= w - 1);
        const bool bx1 = (x0 >= -1) && (x0 <= w - 2);
        const bool by0 = (y0 >= 0) && (y0 <= hh - 1);
        const bool by1 = (y0 >= -1) && (y0 <= hh - 2);

        const float w00 = (1.f - dx) * (1.f - dy);
        const float w01 = (1.f - dx) * dy;
        const float w10 = dx * (1.f - dy);
        const float w11 = dx * dy;

        const float* base = vb + (size_t)st * NEMBED;
        const int i00 = (y0 * w + x0) * NEMBED + lane;

        float v00 = (bx0 && by0) ? base[i00] : 0.f;
        float v01 = (bx0 && by1) ? base[i00 + w * NEMBED] : 0.f;
        float v10 = (bx1 && by0) ? base[i00 + NEMBED] : 0.f;
        float v11 = (bx1 && by1) ? base[i00 + w * NEMBED + NEMBED] : 0.f;

        float sample = w00 * v00 + w01 * v01 + w10 * v10 + w11 * v11;
        acc = fmaf(a, sample, acc);
    }
    g_x[(size_t)r * 256 + h * 32 + lane] = acc;
}

// ---------------------------------------------------------------------------
// kernel_launch
// ---------------------------------------------------------------------------
extern "C" void kernel_launch(void* const* d_in, const int* in_sizes, int n_in,
                              void* d_out, int out_size)
{
    (void)in_sizes; (void)n_in; (void)out_size;
    const float* query = (const float*)d_in[0];
    const float* refp  = (const float*)d_in[1];
    const float* value = (const float*)d_in[2];
    const int*   pad   = (const int*)d_in[3];     // bool -> int32 in harness
    const float* vpk   = (const float*)d_in[4];
    const float* vpb   = (const float*)d_in[5];
    const float* sok   = (const float*)d_in[6];
    const float* sob   = (const float*)d_in[7];
    const float* ak    = (const float*)d_in[8];
    const float* abias = (const float*)d_in[9];
    const float* okern = (const float*)d_in[10];
    const float* obias = (const float*)d_in[11];
    float* out = (float*)d_out;

    float* g_off_p;   cudaGetSymbolAddress((void**)&g_off_p,   g_off);
    float* g_aw_p;    cudaGetSymbolAddress((void**)&g_aw_p,    g_aw);
    float* g_x_p;     cudaGetSymbolAddress((void**)&g_x_p,     g_x);

    dim3 blk(256);
    const int mtiles = (MROWS + 127) / 128;

    // 1) value projection -> g_vproj (scatter layout, bias, mask)
    sgemm_kernel<1><<<dim3(256 / 128, mtiles), blk>>>(value, vpk, nullptr,
                                                      MROWS, 256, vpb, pad);
    // 2) sampling offsets (raw) -> g_off
    sgemm_kernel<0><<<dim3(256 / 128, mtiles), blk>>>(query, sok, g_off_p,
                                                      MROWS, 256, nullptr, nullptr);
    // 3) attention logits (raw) -> g_aw
    sgemm_kernel<0><<<dim3(128 / 128, mtiles), blk>>>(query, ak, g_aw_p,
                                                      MROWS, 128, nullptr, nullptr);
    // 4) softmax + sampling locations
    {
        int tasks = MROWS * HEADS;
        int blocks = (tasks + 7) / 8;    // 8 warps per 256-thread block
        softmax_loc_kernel<<<blocks, blk>>>(abias, sob, refp);
    }
    // 5) bilinear sampling + attention weighting -> g_x
    {
        int tasks = MROWS * HEADS;
        int blocks = (tasks + 7) / 8;
        sampling_kernel<<<blocks, blk>>>();
    }
    // 6) output projection -> d_out
    sgemm_kernel<2><<<dim3(256 / 128, mtiles), blk>>>(g_x_p, okern, out,
                                                      MROWS, 256, obias, nullptr);
}

// round 5
// speedup vs baseline: 1.7636x; 1.7636x over previous
#include <cuda_runtime.h>
#include <cuda_fp16.h>
#include <math.h>

// ---------------------------------------------------------------------------
// Problem constants (MultiScaleDeformableAttention)
// ---------------------------------------------------------------------------
#define BS      2
#define EMBED   256
#define HEADS   8
#define LEVELS  4
#define POINTS  4
#define NEMBED  32
#define LEN_V   18360
#define LEN_Q   18360
#define MROWS   (BS * LEN_Q)       // 36720
#define KDIM    256

// level shapes (h, w): (96,144) (48,72) (24,36) (12,18)
__device__ __constant__ int   c_lw[4]     = {144, 72, 36, 18};
__device__ __constant__ int   c_lh[4]     = { 96, 48, 24, 12};
__device__ __constant__ int   c_lstart[4] = {0, 13824, 17280, 18144};
__device__ __constant__ float c_lwf[4]    = {144.f, 72.f, 36.f, 18.f};
__device__ __constant__ float c_lhf[4]    = { 96.f, 48.f, 24.f, 12.f};

// ---------------------------------------------------------------------------
// Device scratch (allocation-free)
// ---------------------------------------------------------------------------
__device__ __half g_vproj[BS * HEADS * LEN_V * NEMBED];          // fp16 value
__device__ float  g_aw  [MROWS * 128];                           // raw logits
__device__ float  g_loc [MROWS * 256];                           // sampling locs
__device__ float  g_x   [MROWS * 256];                           // sampled feats

// ---------------------------------------------------------------------------
// TF32 helpers
// ---------------------------------------------------------------------------
__device__ __forceinline__ unsigned f2tf32(float f) {
    unsigned r;
    asm("cvt.rna.tf32.f32 %0, %1;" : "=r"(r) : "f"(f));
    return r;
}

__device__ __forceinline__ void mma_tf32(float c[4], const unsigned a[4], const unsigned b[2]) {
    asm volatile(
        "mma.sync.aligned.m16n8k8.row.col.f32.tf32.tf32.f32 "
        "{%0,%1,%2,%3}, {%4,%5,%6,%7}, {%8,%9}, {%0,%1,%2,%3};\n"
        : "+f"(c[0]), "+f"(c[1]), "+f"(c[2]), "+f"(c[3])
        : "r"(a[0]), "r"(a[1]), "r"(a[2]), "r"(a[3]), "r"(b[0]), "r"(b[1]));
}

// ---------------------------------------------------------------------------
// TF32 tensor-core GEMM: C = A[M,256] * B[256,N]
// BM=128 BN=128 BK=32, 256 threads (8 warps: 4(M) x 2(N), warp tile 32x64)
// MODE 0: C[row*N+col] = acc                       (raw logits)
// MODE 1: vproj: + bias, mask, scatter to g_vproj as fp16
// MODE 2: C[row*N+col] = acc + bias[col]           (out projection)
// MODE 3: loc: g_loc[row*256+col] = refp + (acc + sob)/norm
// ---------------------------------------------------------------------------
template <int MODE>
__global__ __launch_bounds__(256)
void tf32_gemm(const float* __restrict__ A,
               const float* __restrict__ Bm,
               float* __restrict__ C,
               int M, int N,
               const float* __restrict__ bias,
               const int* __restrict__ mask,
               const float* __restrict__ refp,
               const float* __restrict__ sob)
{
    __shared__ unsigned As[128][36];   // stride 36: conflict-free frag loads
    __shared__ unsigned Bs[32][132];   // stride 132: conflict-free frag loads

    const int tid  = threadIdx.x;
    const int row0 = blockIdx.y * 128;
    const int col0 = blockIdx.x * 128;
    const int wid  = tid >> 5;
    const int lane = tid & 31;
    const int wm   = wid >> 1;          // 0..3
    const int wn   = wid & 1;           // 0..1
    const int g    = lane >> 2;         // 0..7
    const int tg   = lane & 3;          // 0..3

    float acc[2][8][4];
#pragma unroll
    for (int i = 0; i < 2; i++)
#pragma unroll
        for (int j = 0; j < 8; j++)
#pragma unroll
            for (int v = 0; v < 4; v++) acc[i][j][v] = 0.f;

    for (int k0 = 0; k0 < KDIM; k0 += 32) {
        // ---- load A tile 128x32 (4 float4 per thread), convert to tf32 ----
#pragma unroll
        for (int li = 0; li < 4; li++) {
            int idx = li * 256 + tid;
            int r   = idx >> 3;
            int c4  = (idx & 7) * 4;
            float4 v = make_float4(0.f, 0.f, 0.f, 0.f);
            if (row0 + r < M)
                v = *reinterpret_cast<const float4*>(A + (size_t)(row0 + r) * KDIM + k0 + c4);
            uint4 t;
            t.x = f2tf32(v.x); t.y = f2tf32(v.y); t.z = f2tf32(v.z); t.w = f2tf32(v.w);
            *reinterpret_cast<uint4*>(&As[r][c4]) = t;
        }
        // ---- load B tile 32x128 ----
#pragma unroll
        for (int li = 0; li < 4; li++) {
            int idx = li * 256 + tid;
            int r   = idx >> 5;
            int c4  = (idx & 31) * 4;
            float4 v = *reinterpret_cast<const float4*>(Bm + (size_t)(k0 + r) * N + col0 + c4);
            uint4 t;
            t.x = f2tf32(v.x); t.y = f2tf32(v.y); t.z = f2tf32(v.z); t.w = f2tf32(v.w);
            *reinterpret_cast<uint4*>(&Bs[r][c4]) = t;
        }
        __syncthreads();

#pragma unroll
        for (int kk = 0; kk < 4; kk++) {
            const int kb = kk * 8;
            unsigned a[2][4], b[8][2];
#pragma unroll
            for (int i = 0; i < 2; i++) {
                int row = wm * 32 + i * 16;
                a[i][0] = As[row + g    ][kb + tg    ];
                a[i][1] = As[row + g + 8][kb + tg    ];
                a[i][2] = As[row + g    ][kb + tg + 4];
                a[i][3] = As[row + g + 8][kb + tg + 4];
            }
#pragma unroll
            for (int j = 0; j < 8; j++) {
                int n = wn * 64 + j * 8 + g;
                b[j][0] = Bs[kb + tg    ][n];
                b[j][1] = Bs[kb + tg + 4][n];
            }
#pragma unroll
            for (int i = 0; i < 2; i++)
#pragma unroll
                for (int j = 0; j < 8; j++)
                    mma_tf32(acc[i][j], a[i], b[j]);
        }
        __syncthreads();
    }

    // ---- epilogue ----
#pragma unroll
    for (int i = 0; i < 2; i++) {
        int rbase = row0 + wm * 32 + i * 16 + g;
#pragma unroll
        for (int j = 0; j < 8; j++) {
            int cbase = col0 + wn * 64 + j * 8 + tg * 2;
#pragma unroll
            for (int v = 0; v < 4; v++) {
                int row = rbase + (v >> 1) * 8;
                int col = cbase + (v & 1);
                if (row >= M) continue;
                float val = acc[i][j][v];
                if (MODE == 0) {
                    C[(size_t)row * N + col] = val;
                } else if (MODE == 1) {
                    val += bias[col];
                    if (mask[row] == 0) val = 0.f;
                    int b_  = row / LEN_V;
                    int lv  = row - b_ * LEN_V;
                    int h   = col >> 5;
                    int d   = col & 31;
                    g_vproj[(((size_t)(b_ * HEADS + h)) * LEN_V + lv) * NEMBED + d] =
                        __float2half_rn(val);
                } else if (MODE == 2) {
                    C[(size_t)row * N + col] = val + bias[col];
                } else { // MODE 3: sampling locations
                    int l  = (col >> 3) & 3;
                    int cb = col & 1;
                    float norm = cb ? c_lhf[l] : c_lwf[l];
                    float rp   = refp[((size_t)row * 4 + l) * 2 + cb];
                    g_loc[(size_t)row * 256 + col] = rp + (val + sob[col]) / norm;
                }
            }
        }
    }
}

// ---------------------------------------------------------------------------
// Fused softmax + bilinear sampling + attention weighting.
// One warp per (b,q,h); lane = channel d. g_vproj is fp16.
// ---------------------------------------------------------------------------
__global__ __launch_bounds__(256)
void sampling_kernel(const float* __restrict__ ab)   // attn bias (8,16)
{
    int task = blockIdx.x * (blockDim.x >> 5) + (threadIdx.x >> 5);
    if (task >= MROWS * HEADS) return;
    const int lane = threadIdx.x & 31;
    const int h = task & 7;
    const int r = task >> 3;
    const int b = (r >= LEN_Q) ? 1 : 0;

    // ---- inline softmax over 16 logits (lanes 0..15; xor stays in-group) ----
    float logit = -1e30f;
    if (lane < 16) logit = g_aw[(size_t)r * 128 + h * 16 + lane] + ab[h * 16 + lane];
    float m = logit;
#pragma unroll
    for (int o = 8; o > 0; o >>= 1) m = fmaxf(m, __shfl_xor_sync(0xffffffffu, m, o));
    float e = (lane < 16) ? __expf(logit - m) : 0.f;
    float s = e;
#pragma unroll
    for (int o = 8; o > 0; o >>= 1) s += __shfl_xor_sync(0xffffffffu, s, o);
    const float awv = e / s;   // valid for lanes 0..15

    const float locv = g_loc[(size_t)r * 256 + h * 32 + lane];
    const __half* __restrict__ vb = g_vproj + ((size_t)(b * HEADS + h)) * LEN_V * NEMBED;

    float acc = 0.f;
#pragma unroll
    for (int sIdx = 0; sIdx < LEVELS * POINTS; sIdx++) {
        const int l  = sIdx >> 2;
        const int w  = c_lw[l], hh = c_lh[l], st = c_lstart[l];
        const float gx = __shfl_sync(0xffffffffu, locv, 2 * sIdx);
        const float gy = __shfl_sync(0xffffffffu, locv, 2 * sIdx + 1);
        const float a  = __shfl_sync(0xffffffffu, awv, sIdx);

        const float x = gx * (float)w - 0.5f;
        const float y = gy * (float)hh - 0.5f;
        const float xf = floorf(x), yf = floorf(y);
        const int x0 = (int)xf, y0 = (int)yf;
        const float dx = x - xf, dy = y - yf;

        const bool bx0 = (x0 >= 0) && (x0 <= w - 1);
        const bool bx1 = (x0 >= -1) && (x0 <= w - 2);
        const bool by0 = (y0 >= 0) && (y0 <= hh - 1);
        const bool by1 = (y0 >= -1) && (y0 <= hh - 2);

        const float w00 = (1.f - dx) * (1.f - dy);
        const float w01 = (1.f - dx) * dy;
        const float w10 = dx * (1.f - dy);
        const float w11 = dx * dy;

        const __half* base = vb + (size_t)st * NEMBED;
        const int i00 = (y0 * w + x0) * NEMBED + lane;

        float v00 = (bx0 && by0) ? __half2float(base[i00]) : 0.f;
        float v01 = (bx0 && by1) ? __half2float(base[i00 + w * NEMBED]) : 0.f;
        float v10 = (bx1 && by0) ? __half2float(base[i00 + NEMBED]) : 0.f;
        float v11 = (bx1 && by1) ? __half2float(base[i00 + w * NEMBED + NEMBED]) : 0.f;

        float sample = w00 * v00 + w01 * v01 + w10 * v10 + w11 * v11;
        acc = fmaf(a, sample, acc);
    }
    g_x[(size_t)r * 256 + h * 32 + lane] = acc;
}

// ---------------------------------------------------------------------------
// kernel_launch
// ---------------------------------------------------------------------------
extern "C" void kernel_launch(void* const* d_in, const int* in_sizes, int n_in,
                              void* d_out, int out_size)
{
    (void)in_sizes; (void)n_in; (void)out_size;
    const float* query = (const float*)d_in[0];
    const float* refp  = (const float*)d_in[1];
    const float* value = (const float*)d_in[2];
    const int*   pad   = (const int*)d_in[3];     // bool -> int32
    const float* vpk   = (const float*)d_in[4];
    const float* vpb   = (const float*)d_in[5];
    const float* sok   = (const float*)d_in[6];
    const float* sob   = (const float*)d_in[7];
    const float* ak    = (const float*)d_in[8];
    const float* abias = (const float*)d_in[9];
    const float* okern = (const float*)d_in[10];
    const float* obias = (const float*)d_in[11];
    float* out = (float*)d_out;

    float* g_aw_p; cudaGetSymbolAddress((void**)&g_aw_p, g_aw);
    float* g_x_p;  cudaGetSymbolAddress((void**)&g_x_p,  g_x);

    dim3 blk(256);
    const int mtiles = (MROWS + 127) / 128;   // 287

    // 1) value projection -> g_vproj (fp16, scatter, bias, mask)
    tf32_gemm<1><<<dim3(2, mtiles), blk>>>(value, vpk, nullptr, MROWS, 256,
                                           vpb, pad, nullptr, nullptr);
    // 2) sampling offsets -> g_loc directly (fused loc epilogue)
    tf32_gemm<3><<<dim3(2, mtiles), blk>>>(query, sok, nullptr, MROWS, 256,
                                           nullptr, nullptr, refp, sob);
    // 3) attention logits (raw) -> g_aw
    tf32_gemm<0><<<dim3(1, mtiles), blk>>>(query, ak, g_aw_p, MROWS, 128,
                                           nullptr, nullptr, nullptr, nullptr);
    // 4) fused softmax + bilinear sampling -> g_x
    {
        int tasks  = MROWS * HEADS;
        int blocks = (tasks + 7) / 8;
        sampling_kernel<<<blocks, blk>>>(abias);
    }
    // 5) output projection -> d_out
    tf32_gemm<2><<<dim3(2, mtiles), blk>>>(g_x_p, okern, out, MROWS, 256,
                                           obias, nullptr, nullptr, nullptr);
}